// round 1
// baseline (speedup 1.0000x reference)
#include <cuda_runtime.h>
#include <math.h>

// ---------------- problem constants ----------------
#define BSZ 8
#define TT  2048
#define DD  1024
#define FFD 2048
#define EE  6
#define NTOK (BSZ*TT)      // 16384
#define NF  1025           // T/2+1

// ---------------- scratch (device globals; no allocation allowed) ----------------
__device__ float g_gate[NTOK*EE];     // dense per-expert routing weight (0 if not selected)
__device__ float g_gsh[NTOK];         // sigmoid gate for shared expert
__device__ float g_probs[NTOK*EE];
__device__ int   g_idx[NTOK*2];
__device__ float g_H[NTOK*FFD];                 // 128 MB hidden buffer (reused)
__device__ float g_tmp[NTOK*DD];                // 64 MB expert output buffer
__device__ float g_xc[NTOK*DD];                 // conv-modified input
__device__ float g_cat[BSZ*NF*2048];            // [B,1025,2D]: real||imag
__device__ float g_fo[BSZ*NF*2048];             // fourier MLP output
__device__ float g_Acos[NF*TT];                 // forward DFT cos basis  [1025,2048]
__device__ float g_Asin[NF*TT];                 // forward DFT -sin basis
__device__ float g_Ci[TT*NF];                   // inverse basis (real part)  [2048,1025]
__device__ float g_Si[TT*NF];                   // inverse basis (imag part)

// ---------------- DFT basis init (T=2048 power of two -> exact phase reduction) ----
__global__ void init_dft() {
    int i = blockIdx.x*blockDim.x + threadIdx.x;
    if (i >= NF*TT) return;
    int k = i / TT, t = i % TT;
    int idx = (k*t) & (TT-1);
    float fr = (float)idx / (float)(TT/2);    // angle = pi * fr
    float c = cospif(fr), s = sinpif(fr);
    g_Acos[(long)k*TT + t] = c;
    g_Asin[(long)k*TT + t] = -s;
    float ci, si;
    const float invT = 1.0f/(float)TT;
    if (k == 0)            { ci = invT;                          si = 0.f; }
    else if (k == TT/2)    { ci = ((t & 1) ? -invT : invT);      si = 0.f; }
    else                   { ci = 2.0f*c*invT;                   si = -2.0f*s*invT; }
    g_Ci[(long)t*NF + k] = ci;
    g_Si[(long)t*NF + k] = si;
}

// ---------------- router + shared-expert gate ----------------
__global__ void router_kernel(const float* __restrict__ x,
                              const float* __restrict__ rw, const float* __restrict__ rb,
                              const float* __restrict__ gw, const float* __restrict__ gb) {
    __shared__ float sx[DD];
    __shared__ float slog[8];
    int tok = blockIdx.x;
    const float* xr = x + (long)tok * DD;
    for (int i = threadIdx.x; i < DD; i += blockDim.x) sx[i] = xr[i];
    __syncthreads();
    int w = threadIdx.x >> 5, lane = threadIdx.x & 31;
    if (w < 7) {
        float acc = 0.f;
        if (w < 6) { for (int i = lane; i < DD; i += 32) acc += sx[i] * rw[i*EE + w]; }
        else       { for (int i = lane; i < DD; i += 32) acc += sx[i] * gw[i]; }
        #pragma unroll
        for (int o = 16; o > 0; o >>= 1) acc += __shfl_down_sync(0xffffffffu, acc, o);
        if (lane == 0) slog[w] = acc + (w < 6 ? rb[w] : gb[0]);
    }
    __syncthreads();
    if (threadIdx.x == 0) {
        float l[EE], mx = -1e30f;
        for (int e = 0; e < EE; e++) { l[e] = slog[e]; mx = fmaxf(mx, l[e]); }
        float den = 0.f;
        for (int e = 0; e < EE; e++) { l[e] = expf(l[e]-mx); den += l[e]; }
        float p[EE];
        for (int e = 0; e < EE; e++) { p[e] = l[e]/den; g_probs[tok*EE+e] = p[e]; g_gate[tok*EE+e] = 0.f; }
        // top-2, ties -> lower index (matches lax.top_k)
        int i1 = 0; for (int e = 1; e < EE; e++) if (p[e] > p[i1]) i1 = e;
        int i2 = (i1==0)?1:0;
        for (int e = 0; e < EE; e++) if (e != i1 && p[e] > p[i2]) i2 = e;
        g_gate[tok*EE+i1] = p[i1];
        g_gate[tok*EE+i2] = p[i2];
        g_idx[tok*2]   = i1;
        g_idx[tok*2+1] = i2;
        g_gsh[tok] = 1.0f/(1.0f+expf(-slog[6]));
    }
}

// ---------------- aux loss (deterministic single-block reduction) ----------------
__global__ void aux_kernel(float* __restrict__ out, int out_size) {
    __shared__ float sf[EE][256];
    __shared__ int   si[EE][256];
    float imp[EE]; int cnt[EE];
    for (int e = 0; e < EE; e++) { imp[e] = 0.f; cnt[e] = 0; }
    for (int n = threadIdx.x; n < NTOK; n += 256) {
        #pragma unroll
        for (int e = 0; e < EE; e++) imp[e] += g_probs[n*EE+e];
        cnt[g_idx[n*2]]++; cnt[g_idx[n*2+1]]++;
    }
    for (int e = 0; e < EE; e++) { sf[e][threadIdx.x] = imp[e]; si[e][threadIdx.x] = cnt[e]; }
    __syncthreads();
    for (int s = 128; s > 0; s >>= 1) {
        if (threadIdx.x < s)
            for (int e = 0; e < EE; e++) {
                sf[e][threadIdx.x] += sf[e][threadIdx.x+s];
                si[e][threadIdx.x] += si[e][threadIdx.x+s];
            }
        __syncthreads();
    }
    if (threadIdx.x == 0) {
        float aux = 0.f;
        for (int e = 0; e < EE; e++) {
            float importance = sf[e][0] / (float)NTOK;
            float load = (float)si[e][0] / (2.0f * (float)NTOK);
            aux += load * importance;
        }
        out[out_size-1] = (float)EE * aux;
    }
}

// ---------------- depthwise conv (pad=1, ks=3): xc = x + conv(x) ----------------
__global__ void conv_kernel(const float* __restrict__ x, const float* __restrict__ ck,
                            float* __restrict__ xc) {
    long i = (long)blockIdx.x*blockDim.x + threadIdx.x;
    if (i >= (long)NTOK*DD) return;
    int d = (int)(i % DD);
    long td = i / DD;
    int t = (int)(td % TT);
    float k0 = ck[d*3], k1 = ck[d*3+1], k2 = ck[d*3+2];
    float c = x[i]*k1;
    if (t > 0)     c += x[i-DD]*k0;
    if (t < TT-1)  c += x[i+DD]*k2;
    xc[i] = x[i] + c;
}

// ---------------- combine kernels ----------------
__global__ void scale_store(float* __restrict__ out, const float* __restrict__ t,
                            const float* __restrict__ g) {
    long i = (long)blockIdx.x*blockDim.x + threadIdx.x;
    if (i >= (long)NTOK*DD) return;
    out[i] = t[i] * g[i >> 10];
}
__global__ void add_gated(float* __restrict__ out, const float* __restrict__ t, int eid) {
    long i = (long)blockIdx.x*blockDim.x + threadIdx.x;
    if (i >= (long)NTOK*DD) return;
    out[i] += t[i] * g_gate[(i >> 10)*EE + eid];
}

// ---------------- SIMT fp32 GEMM with packed f32x2 FFMA ----------------
#define BM 128
#define BN 128
#define BK 8
#define TM 8
#define TN 8

typedef unsigned long long u64;
__device__ __forceinline__ u64 ffma2(u64 a, u64 b, u64 c) {
    u64 d; asm("fma.rn.f32x2 %0, %1, %2, %3;" : "=l"(d) : "l"(a), "l"(b), "l"(c)); return d;
}
__device__ __forceinline__ u64 pack_dup(float v) {
    u64 d; unsigned u = __float_as_uint(v);
    asm("mov.b64 %0, {%1, %1};" : "=l"(d) : "r"(u)); return d;
}
__device__ __forceinline__ void unpack2(u64 v, float& lo, float& hi) {
    unsigned a, b; asm("mov.b64 {%0, %1}, %2;" : "=r"(a), "=r"(b) : "l"(v));
    lo = __uint_as_float(a); hi = __uint_as_float(b);
}
__device__ __forceinline__ float gelu_f(float v) {
    return 0.5f*v*(1.0f + erff(v*0.7071067811865475f));
}

// EPI: 0=none, 1=gelu(acc+bias), 2=acc+bias.  BETA: accumulate into C.
template<int EPI, int BETA>
__global__ void gemm_kernel(const float* __restrict__ A, const float* __restrict__ B,
                            float* __restrict__ C, const float* __restrict__ bias,
                            int M, int N, int K, int lda, int ldb, int ldc,
                            long sA, long sB, long sC) {
    A += (long)blockIdx.z * sA;
    B += (long)blockIdx.z * sB;
    C += (long)blockIdx.z * sC;
    __shared__ float As[BK][BM];
    __shared__ float Bs[BK][BN];
    int row0 = blockIdx.y * BM;
    int col0 = blockIdx.x * BN;
    int tid = threadIdx.x;
    int tx = tid & 15, ty = tid >> 4;

    u64 acc2[TM][TN/2];
    #pragma unroll
    for (int i = 0; i < TM; i++)
        #pragma unroll
        for (int j = 0; j < TN/2; j++) acc2[i][j] = 0ULL;

    for (int k0 = 0; k0 < K; k0 += BK) {
        #pragma unroll
        for (int i = 0; i < 4; i++) {
            int idx = tid + i*256;
            int m = idx >> 3, k = idx & 7;
            int gm = row0 + m, gk = k0 + k;
            As[k][m] = (gm < M && gk < K) ? A[(long)gm*lda + gk] : 0.f;
        }
        #pragma unroll
        for (int i = 0; i < 4; i++) {
            int idx = tid + i*256;
            int k = idx >> 7, n = idx & 127;
            int gk = k0 + k, gn = col0 + n;
            Bs[k][n] = (gk < K && gn < N) ? B[(long)gk*ldb + gn] : 0.f;
        }
        __syncthreads();
        #pragma unroll
        for (int k = 0; k < BK; k++) {
            u64 b2[TN/2];
            #pragma unroll
            for (int j = 0; j < TN/2; j++)
                b2[j] = *(const u64*)&Bs[k][tx*TN + 2*j];
            #pragma unroll
            for (int i = 0; i < TM; i++) {
                u64 ad = pack_dup(As[k][ty*TM + i]);
                #pragma unroll
                for (int j = 0; j < TN/2; j++)
                    acc2[i][j] = ffma2(ad, b2[j], acc2[i][j]);
            }
        }
        __syncthreads();
    }

    #pragma unroll
    for (int i = 0; i < TM; i++) {
        int r = row0 + ty*TM + i;
        if (r >= M) continue;
        #pragma unroll
        for (int j = 0; j < TN/2; j++) {
            float v0, v1; unpack2(acc2[i][j], v0, v1);
            int c0 = col0 + tx*TN + 2*j;
            #pragma unroll
            for (int h = 0; h < 2; h++) {
                int c = c0 + h;
                if (c >= N) continue;
                float v = (h == 0) ? v0 : v1;
                if (EPI == 1)      v = gelu_f(v + bias[c]);
                else if (EPI == 2) v = v + bias[c];
                long off = (long)r*ldc + c;
                if (BETA) C[off] += v; else C[off] = v;
            }
        }
    }
}

static void gemm(int epi, int beta,
                 const float* A, const float* B, float* C, const float* bias,
                 int M, int N, int K, int lda, int ldb, int ldc,
                 int batch = 1, long sA = 0, long sB = 0, long sC = 0) {
    dim3 grid((N+BN-1)/BN, (M+BM-1)/BM, batch);
    dim3 blk(256);
    if (epi == 1)              gemm_kernel<1,0><<<grid,blk>>>(A,B,C,bias,M,N,K,lda,ldb,ldc,sA,sB,sC);
    else if (epi == 2)         gemm_kernel<2,0><<<grid,blk>>>(A,B,C,bias,M,N,K,lda,ldb,ldc,sA,sB,sC);
    else if (beta)             gemm_kernel<0,1><<<grid,blk>>>(A,B,C,bias,M,N,K,lda,ldb,ldc,sA,sB,sC);
    else                       gemm_kernel<0,0><<<grid,blk>>>(A,B,C,bias,M,N,K,lda,ldb,ldc,sA,sB,sC);
}

// ---------------- launch ----------------
extern "C" void kernel_launch(void* const* d_in, const int* in_sizes, int n_in,
                              void* d_out, int out_size) {
    const float* x   = (const float*)d_in[0];
    const float* sw1 = (const float*)d_in[1];  const float* sb1 = (const float*)d_in[2];
    const float* sw2 = (const float*)d_in[3];  const float* sb2 = (const float*)d_in[4];
    const float* gw  = (const float*)d_in[5];  const float* gb  = (const float*)d_in[6];
    const float* rw  = (const float*)d_in[7];  const float* rb  = (const float*)d_in[8];
    const float* ck  = (const float*)d_in[9];
    const float* cw1 = (const float*)d_in[10]; const float* cb1 = (const float*)d_in[11];
    const float* cw2 = (const float*)d_in[12]; const float* cb2 = (const float*)d_in[13];
    const float* fw1 = (const float*)d_in[14]; const float* fb1 = (const float*)d_in[15];
    const float* fw2 = (const float*)d_in[16]; const float* fb2 = (const float*)d_in[17];
    const float* mw1 = (const float*)d_in[18]; const float* mb1 = (const float*)d_in[19];
    const float* mw2 = (const float*)d_in[20]; const float* mb2 = (const float*)d_in[21];
    float* out = (float*)d_out;

    void* p;
    cudaGetSymbolAddress(&p, g_H);    float* H    = (float*)p;
    cudaGetSymbolAddress(&p, g_tmp);  float* tmp  = (float*)p;
    cudaGetSymbolAddress(&p, g_xc);   float* xc   = (float*)p;
    cudaGetSymbolAddress(&p, g_cat);  float* cat  = (float*)p;
    cudaGetSymbolAddress(&p, g_fo);   float* fo   = (float*)p;
    cudaGetSymbolAddress(&p, g_Acos); float* Acos = (float*)p;
    cudaGetSymbolAddress(&p, g_Asin); float* Asin = (float*)p;
    cudaGetSymbolAddress(&p, g_Ci);   float* Ci   = (float*)p;
    cudaGetSymbolAddress(&p, g_Si);   float* Si   = (float*)p;
    cudaGetSymbolAddress(&p, g_gsh);  float* gsh  = (float*)p;

    const long NEL = (long)NTOK*DD;
    const int EW_BLOCKS = (int)((NEL + 255) / 256);

    init_dft<<<(NF*TT + 255)/256, 256>>>();
    router_kernel<<<NTOK, 256>>>(x, rw, rb, gw, gb);
    aux_kernel<<<1, 256>>>(out, out_size);

    // shared expert (gated)
    gemm(1, 0, x, sw1, H,   sb1, NTOK, FFD, DD,  DD,  FFD, FFD);
    gemm(2, 0, H, sw2, tmp, sb2, NTOK, DD,  FFD, FFD, DD,  DD);
    scale_store<<<EW_BLOCKS, 256>>>(out, tmp, gsh);

    // plain MLP experts: eid 2, 5
    for (int j = 0; j < 2; j++) {
        gemm(1, 0, x, mw1 + (long)j*DD*FFD, H,   mb1 + j*FFD, NTOK, FFD, DD,  DD,  FFD, FFD);
        gemm(2, 0, H, mw2 + (long)j*FFD*DD, tmp, mb2 + j*DD,  NTOK, DD,  FFD, FFD, DD,  DD);
        add_gated<<<EW_BLOCKS, 256>>>(out, tmp, j == 0 ? 2 : 5);
    }

    // conv experts: eid 0, 3
    for (int j = 0; j < 2; j++) {
        conv_kernel<<<EW_BLOCKS, 256>>>(x, ck + (long)j*DD*3, xc);
        gemm(1, 0, xc, cw1 + (long)j*DD*FFD, H,   cb1 + j*FFD, NTOK, FFD, DD,  DD,  FFD, FFD);
        gemm(2, 0, H,  cw2 + (long)j*FFD*DD, tmp, cb2 + j*DD,  NTOK, DD,  FFD, FFD, DD,  DD);
        add_gated<<<EW_BLOCKS, 256>>>(out, tmp, j == 0 ? 0 : 3);
    }

    // fourier experts: eid 1, 4 — forward DFT computed once, reused by both
    const long sXb = (long)TT*DD;      // x batch stride
    const long sCb = (long)NF*2048;    // cat/fo batch stride
    const long sTb = (long)TT*DD;      // tmp batch stride
    gemm(0, 0, Acos, x, cat,        nullptr, NF, DD, TT, TT, DD, 2048, BSZ, 0, sXb, sCb);
    gemm(0, 0, Asin, x, cat + 1024, nullptr, NF, DD, TT, TT, DD, 2048, BSZ, 0, sXb, sCb);
    for (int j = 0; j < 2; j++) {
        gemm(1, 0, cat, fw1 + (long)j*2048*FFD, H,  fb1 + j*FFD,  BSZ*NF, FFD,  2048, 2048, FFD,  FFD);
        gemm(2, 0, H,   fw2 + (long)j*FFD*2048, fo, fb2 + j*2048, BSZ*NF, 2048, FFD,  FFD,  2048, 2048);
        gemm(0, 0, Ci, fo,        tmp, nullptr, TT, DD, NF, NF, 2048, DD, BSZ, 0, sCb, sTb);
        gemm(0, 1, Si, fo + 1024, tmp, nullptr, TT, DD, NF, NF, 2048, DD, BSZ, 0, sCb, sTb);
        add_gated<<<EW_BLOCKS, 256>>>(out, tmp, j == 0 ? 1 : 4);
    }
}

// round 9
// speedup vs baseline: 3.0726x; 3.0726x over previous
#include <cuda_runtime.h>
#include <math.h>

#define BSZ 8
#define TT  2048
#define DD  1024
#define FFD 2048
#define EE  6
#define NTOK (BSZ*TT)
#define NF  1025
#define NFP 1056
#define KI  (2*NFP)

typedef unsigned int u32;
typedef unsigned long long u64;

// ---------------- scratch ----------------
__device__ float g_gate[NTOK*EE];
__device__ float g_gsh[NTOK];
__device__ float g_probs[NTOK*EE];
__device__ int   g_idx[NTOK*2];
__device__ float g_H[NTOK*(long)FFD];
__device__ float g_xc[NTOK*(long)DD];
__device__ float g_xT[BSZ*(long)DD*TT];
__device__ float g_cat[BSZ*(long)NF*2048];
__device__ float g_fo[BSZ*(long)NF*2048];
__device__ float g_foT[BSZ*(long)DD*KI];
__device__ float g_CiSi[(long)TT*KI];
__device__ float g_Acos[(long)NF*TT];
__device__ float g_Asin[(long)NF*TT];
__device__ float g_WT[36u*1024u*1024u];

// ---------------- init: DFT bases ----------------
__global__ void init_fwd() {
    int i = blockIdx.x*blockDim.x + threadIdx.x;
    if (i >= NF*TT) return;
    int k = i / TT, t = i % TT;
    int idx = (k*t) & (TT-1);
    float fr = (float)idx / (float)(TT/2);
    g_Acos[i] = cospif(fr);
    g_Asin[i] = -sinpif(fr);
}
__global__ void init_inv() {
    long i = (long)blockIdx.x*blockDim.x + threadIdx.x;
    if (i >= (long)TT*KI) return;
    int t = (int)(i / KI), kk = (int)(i % KI);
    int isimag = kk >= NFP;
    int k = isimag ? kk - NFP : kk;
    float v = 0.f;
    const float invT = 1.0f/(float)TT;
    if (k < NF) {
        int idx = (k*t) & (TT-1);
        float fr = (float)idx / (float)(TT/2);
        if (!isimag) {
            if (k == 0) v = invT;
            else if (k == TT/2) v = ((t & 1) ? -invT : invT);
            else v = 2.0f*cospif(fr)*invT;
        } else {
            // SIGN FIX: irfft imag basis is -2*sin(.)/T  (R1-passing convention)
            if (k != 0 && k != TT/2) v = -2.0f*sinpif(fr)*invT;
        }
    }
    g_CiSi[i] = v;
}

// ---------------- router + gates ----------------
__global__ void router_kernel(const float* __restrict__ x,
                              const float* __restrict__ rw, const float* __restrict__ rb,
                              const float* __restrict__ gw, const float* __restrict__ gb) {
    __shared__ float sx[DD];
    __shared__ float slog[8];
    int tok = blockIdx.x;
    const float* xr = x + (long)tok * DD;
    for (int i = threadIdx.x; i < DD; i += blockDim.x) sx[i] = xr[i];
    __syncthreads();
    int w = threadIdx.x >> 5, lane = threadIdx.x & 31;
    if (w < 7) {
        float acc = 0.f;
        if (w < 6) { for (int i = lane; i < DD; i += 32) acc += sx[i] * rw[i*EE + w]; }
        else       { for (int i = lane; i < DD; i += 32) acc += sx[i] * gw[i]; }
        #pragma unroll
        for (int o = 16; o > 0; o >>= 1) acc += __shfl_down_sync(0xffffffffu, acc, o);
        if (lane == 0) slog[w] = acc + (w < 6 ? rb[w] : gb[0]);
    }
    __syncthreads();
    if (threadIdx.x == 0) {
        float l[EE], mx = -1e30f;
        for (int e = 0; e < EE; e++) { l[e] = slog[e]; mx = fmaxf(mx, l[e]); }
        float den = 0.f;
        for (int e = 0; e < EE; e++) { l[e] = expf(l[e]-mx); den += l[e]; }
        float p[EE];
        for (int e = 0; e < EE; e++) { p[e] = l[e]/den; g_probs[tok*EE+e] = p[e]; g_gate[tok*EE+e] = 0.f; }
        int i1 = 0; for (int e = 1; e < EE; e++) if (p[e] > p[i1]) i1 = e;
        int i2 = (i1==0)?1:0;
        for (int e = 0; e < EE; e++) if (e != i1 && p[e] > p[i2]) i2 = e;
        g_gate[tok*EE+i1] = p[i1];
        g_gate[tok*EE+i2] = p[i2];
        g_idx[tok*2]   = i1;
        g_idx[tok*2+1] = i2;
        g_gsh[tok] = 1.0f/(1.0f+expf(-slog[6]));
    }
}

__global__ void aux_kernel(float* __restrict__ out, int out_size) {
    __shared__ float sf[EE][256];
    __shared__ int   si[EE][256];
    float imp[EE]; int cnt[EE];
    for (int e = 0; e < EE; e++) { imp[e] = 0.f; cnt[e] = 0; }
    for (int n = threadIdx.x; n < NTOK; n += 256) {
        #pragma unroll
        for (int e = 0; e < EE; e++) imp[e] += g_probs[n*EE+e];
        cnt[g_idx[n*2]]++; cnt[g_idx[n*2+1]]++;
    }
    for (int e = 0; e < EE; e++) { sf[e][threadIdx.x] = imp[e]; si[e][threadIdx.x] = cnt[e]; }
    __syncthreads();
    for (int s = 128; s > 0; s >>= 1) {
        if (threadIdx.x < s)
            for (int e = 0; e < EE; e++) {
                sf[e][threadIdx.x] += sf[e][threadIdx.x+s];
                si[e][threadIdx.x] += si[e][threadIdx.x+s];
            }
        __syncthreads();
    }
    if (threadIdx.x == 0) {
        float aux = 0.f;
        for (int e = 0; e < EE; e++)
            aux += ((float)si[e][0] / (2.0f*(float)NTOK)) * (sf[e][0] / (float)NTOK);
        out[out_size-1] = (float)EE * aux;
    }
}

// ---------------- conv ----------------
__global__ void conv_kernel(const float* __restrict__ x, const float* __restrict__ ck,
                            float* __restrict__ xc) {
    long i = (long)blockIdx.x*blockDim.x + threadIdx.x;
    if (i >= (long)NTOK*DD) return;
    int d = (int)(i % DD);
    long td = i / DD;
    int t = (int)(td % TT);
    float k0 = ck[d*3], k1 = ck[d*3+1], k2 = ck[d*3+2];
    float c = x[i]*k1;
    if (t > 0)     c += x[i-DD]*k0;
    if (t < TT-1)  c += x[i+DD]*k2;
    xc[i] = x[i] + c;
}

// ---------------- transposes ----------------
__global__ void transpose_k(const float* __restrict__ in, float* __restrict__ out,
                            int R, int C) {
    __shared__ float t[32][33];
    long bo = (long)blockIdx.z * R * C;
    in += bo; out += bo;
    int c0 = blockIdx.x*32, r0 = blockIdx.y*32;
    #pragma unroll
    for (int i = 0; i < 4; i++) {
        int r = r0 + threadIdx.y + i*8, c = c0 + threadIdx.x;
        t[threadIdx.y+i*8][threadIdx.x] = (r < R && c < C) ? in[(long)r*C + c] : 0.f;
    }
    __syncthreads();
    #pragma unroll
    for (int i = 0; i < 4; i++) {
        int c = c0 + threadIdx.y + i*8, r = r0 + threadIdx.x;
        if (c < C && r < R) out[(long)c*R + r] = t[threadIdx.x][threadIdx.y+i*8];
    }
}

__global__ void transpose_fo(const float* __restrict__ fo, float* __restrict__ foT,
                             int coloff, int kbase) {
    __shared__ float t[32][33];
    int b = blockIdx.z;
    const float* in = fo + (long)b*NF*2048;
    float* ob = foT + (long)b*DD*KI;
    int k0 = blockIdx.x*32, d0 = blockIdx.y*32;
    #pragma unroll
    for (int i = 0; i < 4; i++) {
        int k = k0 + threadIdx.y + i*8;
        t[threadIdx.y+i*8][threadIdx.x] = (k < NF) ? in[(long)k*2048 + coloff + d0 + threadIdx.x] : 0.f;
    }
    __syncthreads();
    #pragma unroll
    for (int i = 0; i < 4; i++) {
        int d = d0 + threadIdx.y + i*8;
        ob[(long)d*KI + kbase + k0 + threadIdx.x] = t[threadIdx.x][threadIdx.y+i*8];
    }
}

// ================= tf32 mma.sync GEMM =================
// D[M,N] = A[M,K] @ Bt[N,K]^T; A,Bt K-major. K%16==0, N%128==0, M ragged OK.
#define SPAD 20

__device__ __forceinline__ float gelu_f(float v) {
    return 0.5f*v*(1.0f + erff(v*0.7071067811865475f));
}
__device__ __forceinline__ void cp16(u32 dst, const void* src, int sz) {
    asm volatile("cp.async.ca.shared.global [%0], [%1], 16, %2;" :: "r"(dst), "l"(src), "r"(sz));
}
__device__ __forceinline__ u32 tf32r(float f) {
    u32 r; asm("cvt.rna.tf32.f32 %0, %1;" : "=r"(r) : "f"(f)); return r;
}
__device__ __forceinline__ void mma8(float* c, const u32* a, const u32* b) {
    asm volatile("mma.sync.aligned.m16n8k8.row.col.f32.tf32.tf32.f32 "
        "{%0,%1,%2,%3}, {%4,%5,%6,%7}, {%8,%9}, {%0,%1,%2,%3};"
        : "+f"(c[0]), "+f"(c[1]), "+f"(c[2]), "+f"(c[3])
        : "r"(a[0]), "r"(a[1]), "r"(a[2]), "r"(a[3]), "r"(b[0]), "r"(b[1]));
}

// EPI: 0 store, 1 gelu(v+b), 2 (v+b), 3 out+=(v+b)*gate[r,eid], 4 out=(v+b)*gsh[r],
//      5 out += v*gate[z*TT+r, eid]
template<int EPI>
__global__ void __launch_bounds__(256, 2)
mma_gemm(const float* __restrict__ A, const float* __restrict__ B,
         float* __restrict__ C, const float* __restrict__ bias,
         int M, int N, int K, int lda, int ldb, int ldc,
         long sA, long sB, long sC, int eid)
{
    __shared__ float As[2][128][SPAD];
    __shared__ float Bs[2][128][SPAD];
    A += (long)blockIdx.z * sA;
    B += (long)blockIdx.z * sB;
    C += (long)blockIdx.z * sC;
    const int row0 = blockIdx.y * 128, col0 = blockIdx.x * 128;
    const int tid = threadIdx.x, lane = tid & 31, wid = tid >> 5;
    const int wm = (wid >> 2) * 64, wn = (wid & 3) * 32;
    const u32 sa = (u32)__cvta_generic_to_shared(&As[0][0][0]);
    const u32 sb = (u32)__cvta_generic_to_shared(&Bs[0][0][0]);
    const int g4 = lane >> 2, q4 = lane & 3;

    float acc[4][4][4];
    #pragma unroll
    for (int mi = 0; mi < 4; mi++)
        #pragma unroll
        for (int ni = 0; ni < 4; ni++)
            #pragma unroll
            for (int q = 0; q < 4; q++) acc[mi][ni][q] = 0.f;

    const int ldrow = tid >> 2, ldq = tid & 3;
    const int nk = K / 16;

    auto loadStage = [&](int ic, int buf) {
        int k0 = ic * 16;
        #pragma unroll
        for (int i = 0; i < 2; i++) {
            int row = ldrow + i*64;
            int gm = row0 + row;
            bool ok = gm < M;
            const float* srcA = A + (ok ? ((long)gm*lda + k0 + ldq*4) : 0);
            cp16(sa + (u32)(((buf*128 + row)*SPAD + ldq*4)*4), srcA, ok ? 16 : 0);
            const float* srcB = B + (long)(col0 + row)*ldb + k0 + ldq*4;
            cp16(sb + (u32)(((buf*128 + row)*SPAD + ldq*4)*4), srcB, 16);
        }
        asm volatile("cp.async.commit_group;" ::: "memory");
    };

    loadStage(0, 0);

    for (int ic = 0; ic < nk; ic++) {
        const int buf = ic & 1;
        asm volatile("cp.async.wait_group 0;" ::: "memory");
        __syncthreads();
        if (ic + 1 < nk) loadStage(ic + 1, buf ^ 1);
        #pragma unroll
        for (int ks = 0; ks < 2; ks++) {
            u32 areg[4][4], breg[4][2];
            #pragma unroll
            for (int mi = 0; mi < 4; mi++) {
                const float* ap = &As[buf][wm + mi*16 + g4][ks*8 + q4];
                areg[mi][0] = tf32r(ap[0]);
                areg[mi][1] = tf32r(ap[8*SPAD]);
                areg[mi][2] = tf32r(ap[4]);
                areg[mi][3] = tf32r(ap[8*SPAD + 4]);
            }
            #pragma unroll
            for (int ni = 0; ni < 4; ni++) {
                const float* bp = &Bs[buf][wn + ni*8 + g4][ks*8 + q4];
                breg[ni][0] = tf32r(bp[0]);
                breg[ni][1] = tf32r(bp[4]);
            }
            #pragma unroll
            for (int mi = 0; mi < 4; mi++)
                #pragma unroll
                for (int ni = 0; ni < 4; ni++)
                    mma8(acc[mi][ni], areg[mi], breg[ni]);
        }
        __syncthreads();
    }

    // ---- epilogue (C frag: rows g4 / g4+8, cols 2*q4, 2*q4+1) ----
    #pragma unroll
    for (int mi = 0; mi < 4; mi++) {
        #pragma unroll
        for (int h = 0; h < 2; h++) {
            int r = row0 + wm + mi*16 + g4 + h*8;
            if (r >= M) continue;
            float gmul = 1.f;
            if (EPI == 3) gmul = g_gate[(long)r*EE + eid];
            if (EPI == 4) gmul = g_gsh[r];
            if (EPI == 5) gmul = g_gate[((long)blockIdx.z*TT + r)*EE + eid];
            float* crow = C + (long)r*ldc;
            #pragma unroll
            for (int ni = 0; ni < 4; ni++) {
                int col = col0 + wn + ni*8 + 2*q4;
                float v0 = acc[mi][ni][h*2 + 0];
                float v1 = acc[mi][ni][h*2 + 1];
                if (EPI == 1 || EPI == 2 || EPI == 3 || EPI == 4) {
                    v0 += bias[col]; v1 += bias[col+1];
                }
                float2 o;
                if (EPI == 1) { o.x = gelu_f(v0); o.y = gelu_f(v1); }
                else if (EPI == 3 || EPI == 5) {
                    float2 pv = *(float2*)(crow + col);
                    o.x = pv.x + v0*gmul; o.y = pv.y + v1*gmul;
                } else if (EPI == 4) { o.x = v0*gmul; o.y = v1*gmul; }
                else { o.x = v0; o.y = v1; }
                *(float2*)(crow + col) = o;
            }
        }
    }
}

// ---------------- host dispatch ----------------
static void gemm(int epi, const float* A, const float* B, float* C, const float* bias,
                 int M, int N, int K, int lda, int ldb, int ldc,
                 int batch = 1, long sA = 0, long sB = 0, long sC = 0, int eid = 0) {
    dim3 grid(N/128, (M+127)/128, batch);
    dim3 blk(256);
    switch (epi) {
        case 0: mma_gemm<0><<<grid,blk>>>(A,B,C,bias,M,N,K,lda,ldb,ldc,sA,sB,sC,eid); break;
        case 1: mma_gemm<1><<<grid,blk>>>(A,B,C,bias,M,N,K,lda,ldb,ldc,sA,sB,sC,eid); break;
        case 2: mma_gemm<2><<<grid,blk>>>(A,B,C,bias,M,N,K,lda,ldb,ldc,sA,sB,sC,eid); break;
        case 3: mma_gemm<3><<<grid,blk>>>(A,B,C,bias,M,N,K,lda,ldb,ldc,sA,sB,sC,eid); break;
        case 4: mma_gemm<4><<<grid,blk>>>(A,B,C,bias,M,N,K,lda,ldb,ldc,sA,sB,sC,eid); break;
        case 5: mma_gemm<5><<<grid,blk>>>(A,B,C,bias,M,N,K,lda,ldb,ldc,sA,sB,sC,eid); break;
    }
}

static void transpose(const float* in, float* out, int R, int C, int batch = 1) {
    dim3 grid((C+31)/32, (R+31)/32, batch);
    transpose_k<<<grid, dim3(32,8)>>>(in, out, R, C);
}

extern "C" void kernel_launch(void* const* d_in, const int* in_sizes, int n_in,
                              void* d_out, int out_size) {
    const float* x   = (const float*)d_in[0];
    const float* sw1 = (const float*)d_in[1];  const float* sb1 = (const float*)d_in[2];
    const float* sw2 = (const float*)d_in[3];  const float* sb2 = (const float*)d_in[4];
    const float* gw  = (const float*)d_in[5];  const float* gb  = (const float*)d_in[6];
    const float* rw  = (const float*)d_in[7];  const float* rb  = (const float*)d_in[8];
    const float* ck  = (const float*)d_in[9];
    const float* cw1 = (const float*)d_in[10]; const float* cb1 = (const float*)d_in[11];
    const float* cw2 = (const float*)d_in[12]; const float* cb2 = (const float*)d_in[13];
    const float* fw1 = (const float*)d_in[14]; const float* fb1 = (const float*)d_in[15];
    const float* fw2 = (const float*)d_in[16]; const float* fb2 = (const float*)d_in[17];
    const float* mw1 = (const float*)d_in[18]; const float* mb1 = (const float*)d_in[19];
    const float* mw2 = (const float*)d_in[20]; const float* mb2 = (const float*)d_in[21];
    float* out = (float*)d_out;

    void* p;
    cudaGetSymbolAddress(&p, g_H);    float* H    = (float*)p;
    cudaGetSymbolAddress(&p, g_xc);   float* xc   = (float*)p;
    cudaGetSymbolAddress(&p, g_xT);   float* xT   = (float*)p;
    cudaGetSymbolAddress(&p, g_cat);  float* cat  = (float*)p;
    cudaGetSymbolAddress(&p, g_fo);   float* fo   = (float*)p;
    cudaGetSymbolAddress(&p, g_foT);  float* foT  = (float*)p;
    cudaGetSymbolAddress(&p, g_CiSi); float* CiSi = (float*)p;
    cudaGetSymbolAddress(&p, g_Acos); float* Acos = (float*)p;
    cudaGetSymbolAddress(&p, g_Asin); float* Asin = (float*)p;
    cudaGetSymbolAddress(&p, g_WT);   float* WT   = (float*)p;

    const long M1 = 1048576L;
    float* sw1T = WT;
    float* sw2T = WT + 2*M1;
    float* mw1T = WT + 4*M1;
    float* mw2T = WT + 8*M1;
    float* cw1T = WT + 12*M1;
    float* cw2T = WT + 16*M1;
    float* fw1T = WT + 20*M1;
    float* fw2T = WT + 28*M1;

    init_fwd<<<(NF*TT + 255)/256, 256>>>();
    init_inv<<<(int)(((long)TT*KI + 255)/256), 256>>>();
    transpose(sw1, sw1T, DD, FFD);
    transpose(sw2, sw2T, FFD, DD);
    transpose(mw1, mw1T, DD, FFD, 2);
    transpose(mw2, mw2T, FFD, DD, 2);
    transpose(cw1, cw1T, DD, FFD, 2);
    transpose(cw2, cw2T, FFD, DD, 2);
    transpose(fw1, fw1T, 2048, FFD, 2);
    transpose(fw2, fw2T, FFD, 2048, 2);
    transpose(x, xT, TT, DD, BSZ);

    router_kernel<<<NTOK, 256>>>(x, rw, rb, gw, gb);
    aux_kernel<<<1, 256>>>(out, out_size);

    const long NEL = (long)NTOK*DD;
    const int EW_BLOCKS = (int)((NEL + 255) / 256);

    // shared expert
    gemm(1, x, sw1T, H,   sb1, NTOK, FFD, DD,  DD,  DD,  FFD);
    gemm(4, H, sw2T, out, sb2, NTOK, DD,  FFD, FFD, FFD, DD);

    // plain MLP experts (eid 2,5)
    for (int j = 0; j < 2; j++) {
        gemm(1, x, mw1T + (long)j*2*M1, H,   mb1 + j*FFD, NTOK, FFD, DD,  DD,  DD,  FFD);
        gemm(3, H, mw2T + (long)j*2*M1, out, mb2 + j*DD,  NTOK, DD,  FFD, FFD, FFD, DD, 1,0,0,0, j==0?2:5);
    }

    // conv experts (eid 0,3)
    for (int j = 0; j < 2; j++) {
        conv_kernel<<<EW_BLOCKS, 256>>>(x, ck + (long)j*DD*3, xc);
        gemm(1, xc, cw1T + (long)j*2*M1, H,   cb1 + j*FFD, NTOK, FFD, DD,  DD,  DD,  FFD);
        gemm(3, H,  cw2T + (long)j*2*M1, out, cb2 + j*DD,  NTOK, DD,  FFD, FFD, FFD, DD, 1,0,0,0, j==0?0:3);
    }

    // fourier experts (eid 1,4)
    gemm(0, Acos, xT, cat,        nullptr, NF, DD, TT, TT, TT, 2048, BSZ, 0, (long)DD*TT, (long)NF*2048);
    gemm(0, Asin, xT, cat + 1024, nullptr, NF, DD, TT, TT, TT, 2048, BSZ, 0, (long)DD*TT, (long)NF*2048);
    for (int j = 0; j < 2; j++) {
        gemm(1, cat, fw1T + (long)j*4*M1, H,  fb1 + j*FFD,  BSZ*NF, FFD,  2048, 2048, 2048, FFD);
        gemm(2, H,   fw2T + (long)j*4*M1, fo, fb2 + j*2048, BSZ*NF, 2048, FFD,  FFD,  FFD,  2048);
        transpose_fo<<<dim3(33, 32, BSZ), dim3(32,8)>>>(fo, foT, 0, 0);
        transpose_fo<<<dim3(33, 32, BSZ), dim3(32,8)>>>(fo, foT, 1024, NFP);
        gemm(5, CiSi, foT, out, nullptr, TT, DD, KI, KI, KI, DD, BSZ, 0, (long)DD*KI, (long)TT*DD, j==0?1:4);
    }
}

// round 12
// speedup vs baseline: 3.0858x; 1.0043x over previous
#include <cuda_runtime.h>
#include <math.h>

#define BSZ 8
#define TT  2048
#define DD  1024
#define FFD 2048
#define EE  6
#define NTOK (BSZ*TT)
#define NF  1025
#define NFP 1056
#define KI  (2*NFP)

typedef unsigned int u32;
typedef unsigned long long u64;

// ---------------- scratch ----------------
__device__ float g_gate[NTOK*EE];
__device__ float g_gsh[NTOK];
__device__ float g_probs[NTOK*EE];
__device__ int   g_idx[NTOK*2];
__device__ float g_H[NTOK*(long)FFD];
__device__ float g_xc[NTOK*(long)DD];
__device__ float g_xT[BSZ*(long)DD*TT];
__device__ float g_cat[BSZ*(long)NF*2048];
__device__ float g_fo[BSZ*(long)NF*2048];
__device__ float g_foT[BSZ*(long)DD*KI];
__device__ float g_CiSi[(long)TT*KI];
__device__ float g_Acos[(long)NF*TT];
__device__ float g_Asin[(long)NF*TT];
__device__ float g_WT[36u*1024u*1024u];

// ---------------- init: DFT bases ----------------
__global__ void init_fwd() {
    int i = blockIdx.x*blockDim.x + threadIdx.x;
    if (i >= NF*TT) return;
    int k = i / TT, t = i % TT;
    int idx = (k*t) & (TT-1);
    float fr = (float)idx / (float)(TT/2);
    g_Acos[i] = cospif(fr);
    g_Asin[i] = -sinpif(fr);
}
__global__ void init_inv() {
    long i = (long)blockIdx.x*blockDim.x + threadIdx.x;
    if (i >= (long)TT*KI) return;
    int t = (int)(i / KI), kk = (int)(i % KI);
    int isimag = kk >= NFP;
    int k = isimag ? kk - NFP : kk;
    float v = 0.f;
    const float invT = 1.0f/(float)TT;
    if (k < NF) {
        int idx = (k*t) & (TT-1);
        float fr = (float)idx / (float)(TT/2);
        if (!isimag) {
            if (k == 0) v = invT;
            else if (k == TT/2) v = ((t & 1) ? -invT : invT);
            else v = 2.0f*cospif(fr)*invT;
        } else {
            if (k != 0 && k != TT/2) v = -2.0f*sinpif(fr)*invT;
        }
    }
    g_CiSi[i] = v;
}

// ---------------- router + gates ----------------
__global__ void router_kernel(const float* __restrict__ x,
                              const float* __restrict__ rw, const float* __restrict__ rb,
                              const float* __restrict__ gw, const float* __restrict__ gb) {
    __shared__ float sx[DD];
    __shared__ float slog[8];
    int tok = blockIdx.x;
    const float* xr = x + (long)tok * DD;
    for (int i = threadIdx.x; i < DD; i += blockDim.x) sx[i] = xr[i];
    __syncthreads();
    int w = threadIdx.x >> 5, lane = threadIdx.x & 31;
    if (w < 7) {
        float acc = 0.f;
        if (w < 6) { for (int i = lane; i < DD; i += 32) acc += sx[i] * rw[i*EE + w]; }
        else       { for (int i = lane; i < DD; i += 32) acc += sx[i] * gw[i]; }
        #pragma unroll
        for (int o = 16; o > 0; o >>= 1) acc += __shfl_down_sync(0xffffffffu, acc, o);
        if (lane == 0) slog[w] = acc + (w < 6 ? rb[w] : gb[0]);
    }
    __syncthreads();
    if (threadIdx.x == 0) {
        float l[EE], mx = -1e30f;
        for (int e = 0; e < EE; e++) { l[e] = slog[e]; mx = fmaxf(mx, l[e]); }
        float den = 0.f;
        for (int e = 0; e < EE; e++) { l[e] = expf(l[e]-mx); den += l[e]; }
        float p[EE];
        for (int e = 0; e < EE; e++) { p[e] = l[e]/den; g_probs[tok*EE+e] = p[e]; g_gate[tok*EE+e] = 0.f; }
        int i1 = 0; for (int e = 1; e < EE; e++) if (p[e] > p[i1]) i1 = e;
        int i2 = (i1==0)?1:0;
        for (int e = 0; e < EE; e++) if (e != i1 && p[e] > p[i2]) i2 = e;
        g_gate[tok*EE+i1] = p[i1];
        g_gate[tok*EE+i2] = p[i2];
        g_idx[tok*2]   = i1;
        g_idx[tok*2+1] = i2;
        g_gsh[tok] = 1.0f/(1.0f+expf(-slog[6]));
    }
}

__global__ void aux_kernel(float* __restrict__ out, int out_size) {
    __shared__ float sf[EE][256];
    __shared__ int   si[EE][256];
    float imp[EE]; int cnt[EE];
    for (int e = 0; e < EE; e++) { imp[e] = 0.f; cnt[e] = 0; }
    for (int n = threadIdx.x; n < NTOK; n += 256) {
        #pragma unroll
        for (int e = 0; e < EE; e++) imp[e] += g_probs[n*EE+e];
        cnt[g_idx[n*2]]++; cnt[g_idx[n*2+1]]++;
    }
    for (int e = 0; e < EE; e++) { sf[e][threadIdx.x] = imp[e]; si[e][threadIdx.x] = cnt[e]; }
    __syncthreads();
    for (int s = 128; s > 0; s >>= 1) {
        if (threadIdx.x < s)
            for (int e = 0; e < EE; e++) {
                sf[e][threadIdx.x] += sf[e][threadIdx.x+s];
                si[e][threadIdx.x] += si[e][threadIdx.x+s];
            }
        __syncthreads();
    }
    if (threadIdx.x == 0) {
        float aux = 0.f;
        for (int e = 0; e < EE; e++)
            aux += ((float)si[e][0] / (2.0f*(float)NTOK)) * (sf[e][0] / (float)NTOK);
        out[out_size-1] = (float)EE * aux;
    }
}

// ---------------- conv ----------------
__global__ void conv_kernel(const float* __restrict__ x, const float* __restrict__ ck,
                            float* __restrict__ xc) {
    long i = (long)blockIdx.x*blockDim.x + threadIdx.x;
    if (i >= (long)NTOK*DD) return;
    int d = (int)(i % DD);
    long td = i / DD;
    int t = (int)(td % TT);
    float k0 = ck[d*3], k1 = ck[d*3+1], k2 = ck[d*3+2];
    float c = x[i]*k1;
    if (t > 0)     c += x[i-DD]*k0;
    if (t < TT-1)  c += x[i+DD]*k2;
    xc[i] = x[i] + c;
}

// ---------------- transposes ----------------
__global__ void transpose_k(const float* __restrict__ in, float* __restrict__ out,
                            int R, int C) {
    __shared__ float t[32][33];
    long bo = (long)blockIdx.z * R * C;
    in += bo; out += bo;
    int c0 = blockIdx.x*32, r0 = blockIdx.y*32;
    #pragma unroll
    for (int i = 0; i < 4; i++) {
        int r = r0 + threadIdx.y + i*8, c = c0 + threadIdx.x;
        t[threadIdx.y+i*8][threadIdx.x] = (r < R && c < C) ? in[(long)r*C + c] : 0.f;
    }
    __syncthreads();
    #pragma unroll
    for (int i = 0; i < 4; i++) {
        int c = c0 + threadIdx.y + i*8, r = r0 + threadIdx.x;
        if (c < C && r < R) out[(long)c*R + r] = t[threadIdx.x][threadIdx.y+i*8];
    }
}

__global__ void transpose_fo(const float* __restrict__ fo, float* __restrict__ foT,
                             int coloff, int kbase) {
    __shared__ float t[32][33];
    int b = blockIdx.z;
    const float* in = fo + (long)b*NF*2048;
    float* ob = foT + (long)b*DD*KI;
    int k0 = blockIdx.x*32, d0 = blockIdx.y*32;
    #pragma unroll
    for (int i = 0; i < 4; i++) {
        int k = k0 + threadIdx.y + i*8;
        t[threadIdx.y+i*8][threadIdx.x] = (k < NF) ? in[(long)k*2048 + coloff + d0 + threadIdx.x] : 0.f;
    }
    __syncthreads();
    #pragma unroll
    for (int i = 0; i < 4; i++) {
        int d = d0 + threadIdx.y + i*8;
        ob[(long)d*KI + kbase + k0 + threadIdx.x] = t[threadIdx.x][threadIdx.y+i*8];
    }
}

// ================= tf32 mma.sync GEMM, 3-stage cp.async pipeline =================
// D[M,N] = A[M,K] @ Bt[N,K]^T; A,Bt K-major. K%16==0, N%128==0, M ragged OK.
#define SPAD 20
#define NSTAGE 3
#define TILE_FLOATS (128*SPAD)                       // one operand tile
#define SMEM_DYN (NSTAGE*2*TILE_FLOATS*4)            // bytes

__device__ __forceinline__ float gelu_f(float v) {
    return 0.5f*v*(1.0f + erff(v*0.7071067811865475f));
}
__device__ __forceinline__ void cp16(u32 dst, const void* src, int sz) {
    asm volatile("cp.async.ca.shared.global [%0], [%1], 16, %2;" :: "r"(dst), "l"(src), "r"(sz));
}
__device__ __forceinline__ u32 tf32r(float f) {
    u32 r; asm("cvt.rna.tf32.f32 %0, %1;" : "=r"(r) : "f"(f)); return r;
}
__device__ __forceinline__ void mma8(float* c, const u32* a, const u32* b) {
    asm volatile("mma.sync.aligned.m16n8k8.row.col.f32.tf32.tf32.f32 "
        "{%0,%1,%2,%3}, {%4,%5,%6,%7}, {%8,%9}, {%0,%1,%2,%3};"
        : "+f"(c[0]), "+f"(c[1]), "+f"(c[2]), "+f"(c[3])
        : "r"(a[0]), "r"(a[1]), "r"(a[2]), "r"(a[3]), "r"(b[0]), "r"(b[1]));
}

// EPI: 0 store, 1 gelu(v+b), 2 (v+b), 3 out+=(v+b)*gate[r,eid], 4 out=(v+b)*gsh[r],
//      5 out += v*gate[z*TT+r, eid]
template<int EPI>
__global__ void __launch_bounds__(256, 2)
mma_gemm(const float* __restrict__ A, const float* __restrict__ B,
         float* __restrict__ C, const float* __restrict__ bias,
         int M, int N, int K, int lda, int ldb, int ldc,
         long sA, long sB, long sC, int eid)
{
    extern __shared__ float smp[];
    float* Asm = smp;                          // [NSTAGE][128][SPAD]
    float* Bsm = smp + NSTAGE*TILE_FLOATS;     // [NSTAGE][128][SPAD]
    A += (long)blockIdx.z * sA;
    B += (long)blockIdx.z * sB;
    C += (long)blockIdx.z * sC;
    const int row0 = blockIdx.y * 128, col0 = blockIdx.x * 128;
    const int tid = threadIdx.x, lane = tid & 31, wid = tid >> 5;
    const int wm = (wid >> 2) * 64, wn = (wid & 3) * 32;
    const u32 sa = (u32)__cvta_generic_to_shared(Asm);
    const u32 sb = (u32)__cvta_generic_to_shared(Bsm);
    const int g4 = lane >> 2, q4 = lane & 3;

    float acc[4][4][4];
    #pragma unroll
    for (int mi = 0; mi < 4; mi++)
        #pragma unroll
        for (int ni = 0; ni < 4; ni++)
            #pragma unroll
            for (int q = 0; q < 4; q++) acc[mi][ni][q] = 0.f;

    const int ldrow = tid >> 2, ldq = tid & 3;
    const int nk = K / 16;

    auto loadStage = [&](int ic, int buf) {
        int k0 = ic * 16;
        #pragma unroll
        for (int i = 0; i < 2; i++) {
            int row = ldrow + i*64;
            int gm = row0 + row;
            bool ok = gm < M;
            const float* srcA = A + (ok ? ((long)gm*lda + k0 + ldq*4) : 0);
            cp16(sa + (u32)(((buf*128 + row)*SPAD + ldq*4)*4), srcA, ok ? 16 : 0);
            const float* srcB = B + (long)(col0 + row)*ldb + k0 + ldq*4;
            cp16(sb + (u32)(((buf*128 + row)*SPAD + ldq*4)*4), srcB, 16);
        }
        asm volatile("cp.async.commit_group;" ::: "memory");
    };

    // prologue: stages 0,1 in flight
    loadStage(0, 0);
    if (nk > 1) loadStage(1, 1);

    int buf = 0;
    for (int ic = 0; ic < nk; ic++) {
        asm volatile("cp.async.wait_group 1;" ::: "memory");
        __syncthreads();
        if (ic + 2 < nk) loadStage(ic + 2, (ic + 2) % NSTAGE);

        const float* Ab = Asm + buf*TILE_FLOATS;
        const float* Bb = Bsm + buf*TILE_FLOATS;
        #pragma unroll
        for (int ks = 0; ks < 2; ks++) {
            u32 areg[4][4], breg[4][2];
            #pragma unroll
            for (int mi = 0; mi < 4; mi++) {
                const float* ap = Ab + (wm + mi*16 + g4)*SPAD + ks*8 + q4;
                areg[mi][0] = tf32r(ap[0]);
                areg[mi][1] = tf32r(ap[8*SPAD]);
                areg[mi][2] = tf32r(ap[4]);
                areg[mi][3] = tf32r(ap[8*SPAD + 4]);
            }
            #pragma unroll
            for (int ni = 0; ni < 4; ni++) {
                const float* bp = Bb + (wn + ni*8 + g4)*SPAD + ks*8 + q4;
                breg[ni][0] = tf32r(bp[0]);
                breg[ni][1] = tf32r(bp[4]);
            }
            #pragma unroll
            for (int mi = 0; mi < 4; mi++)
                #pragma unroll
                for (int ni = 0; ni < 4; ni++)
                    mma8(acc[mi][ni], areg[mi], breg[ni]);
        }
        buf = (buf + 1 == NSTAGE) ? 0 : buf + 1;
    }

    // ---- epilogue (C frag: rows g4 / g4+8, cols 2*q4, 2*q4+1) ----
    #pragma unroll
    for (int mi = 0; mi < 4; mi++) {
        #pragma unroll
        for (int h = 0; h < 2; h++) {
            int r = row0 + wm + mi*16 + g4 + h*8;
            if (r >= M) continue;
            float gmul = 1.f;
            if (EPI == 3) gmul = g_gate[(long)r*EE + eid];
            if (EPI == 4) gmul = g_gsh[r];
            if (EPI == 5) gmul = g_gate[((long)blockIdx.z*TT + r)*EE + eid];
            float* crow = C + (long)r*ldc;
            #pragma unroll
            for (int ni = 0; ni < 4; ni++) {
                int col = col0 + wn + ni*8 + 2*q4;
                float v0 = acc[mi][ni][h*2 + 0];
                float v1 = acc[mi][ni][h*2 + 1];
                if (EPI == 1 || EPI == 2 || EPI == 3 || EPI == 4) {
                    v0 += bias[col]; v1 += bias[col+1];
                }
                float2 o;
                if (EPI == 1) { o.x = gelu_f(v0); o.y = gelu_f(v1); }
                else if (EPI == 3 || EPI == 5) {
                    float2 pv = *(float2*)(crow + col);
                    o.x = pv.x + v0*gmul; o.y = pv.y + v1*gmul;
                } else if (EPI == 4) { o.x = v0*gmul; o.y = v1*gmul; }
                else { o.x = v0; o.y = v1; }
                *(float2*)(crow + col) = o;
            }
        }
    }
}

// ---------------- host dispatch ----------------
static void set_smem_attrs() {
    static int done = 0;
    if (done) return;
    cudaFuncSetAttribute(mma_gemm<0>, cudaFuncAttributeMaxDynamicSharedMemorySize, SMEM_DYN);
    cudaFuncSetAttribute(mma_gemm<1>, cudaFuncAttributeMaxDynamicSharedMemorySize, SMEM_DYN);
    cudaFuncSetAttribute(mma_gemm<2>, cudaFuncAttributeMaxDynamicSharedMemorySize, SMEM_DYN);
    cudaFuncSetAttribute(mma_gemm<3>, cudaFuncAttributeMaxDynamicSharedMemorySize, SMEM_DYN);
    cudaFuncSetAttribute(mma_gemm<4>, cudaFuncAttributeMaxDynamicSharedMemorySize, SMEM_DYN);
    cudaFuncSetAttribute(mma_gemm<5>, cudaFuncAttributeMaxDynamicSharedMemorySize, SMEM_DYN);
    done = 1;
}

static void gemm(int epi, const float* A, const float* B, float* C, const float* bias,
                 int M, int N, int K, int lda, int ldb, int ldc,
                 int batch = 1, long sA = 0, long sB = 0, long sC = 0, int eid = 0) {
    dim3 grid(N/128, (M+127)/128, batch);
    dim3 blk(256);
    switch (epi) {
        case 0: mma_gemm<0><<<grid,blk,SMEM_DYN>>>(A,B,C,bias,M,N,K,lda,ldb,ldc,sA,sB,sC,eid); break;
        case 1: mma_gemm<1><<<grid,blk,SMEM_DYN>>>(A,B,C,bias,M,N,K,lda,ldb,ldc,sA,sB,sC,eid); break;
        case 2: mma_gemm<2><<<grid,blk,SMEM_DYN>>>(A,B,C,bias,M,N,K,lda,ldb,ldc,sA,sB,sC,eid); break;
        case 3: mma_gemm<3><<<grid,blk,SMEM_DYN>>>(A,B,C,bias,M,N,K,lda,ldb,ldc,sA,sB,sC,eid); break;
        case 4: mma_gemm<4><<<grid,blk,SMEM_DYN>>>(A,B,C,bias,M,N,K,lda,ldb,ldc,sA,sB,sC,eid); break;
        case 5: mma_gemm<5><<<grid,blk,SMEM_DYN>>>(A,B,C,bias,M,N,K,lda,ldb,ldc,sA,sB,sC,eid); break;
    }
}

static void transpose(const float* in, float* out, int R, int C, int batch = 1) {
    dim3 grid((C+31)/32, (R+31)/32, batch);
    transpose_k<<<grid, dim3(32,8)>>>(in, out, R, C);
}

extern "C" void kernel_launch(void* const* d_in, const int* in_sizes, int n_in,
                              void* d_out, int out_size) {
    const float* x   = (const float*)d_in[0];
    const float* sw1 = (const float*)d_in[1];  const float* sb1 = (const float*)d_in[2];
    const float* sw2 = (const float*)d_in[3];  const float* sb2 = (const float*)d_in[4];
    const float* gw  = (const float*)d_in[5];  const float* gb  = (const float*)d_in[6];
    const float* rw  = (const float*)d_in[7];  const float* rb  = (const float*)d_in[8];
    const float* ck  = (const float*)d_in[9];
    const float* cw1 = (const float*)d_in[10]; const float* cb1 = (const float*)d_in[11];
    const float* cw2 = (const float*)d_in[12]; const float* cb2 = (const float*)d_in[13];
    const float* fw1 = (const float*)d_in[14]; const float* fb1 = (const float*)d_in[15];
    const float* fw2 = (const float*)d_in[16]; const float* fb2 = (const float*)d_in[17];
    const float* mw1 = (const float*)d_in[18]; const float* mb1 = (const float*)d_in[19];
    const float* mw2 = (const float*)d_in[20]; const float* mb2 = (const float*)d_in[21];
    float* out = (float*)d_out;

    set_smem_attrs();

    void* p;
    cudaGetSymbolAddress(&p, g_H);    float* H    = (float*)p;
    cudaGetSymbolAddress(&p, g_xc);   float* xc   = (float*)p;
    cudaGetSymbolAddress(&p, g_xT);   float* xT   = (float*)p;
    cudaGetSymbolAddress(&p, g_cat);  float* cat  = (float*)p;
    cudaGetSymbolAddress(&p, g_fo);   float* fo   = (float*)p;
    cudaGetSymbolAddress(&p, g_foT);  float* foT  = (float*)p;
    cudaGetSymbolAddress(&p, g_CiSi); float* CiSi = (float*)p;
    cudaGetSymbolAddress(&p, g_Acos); float* Acos = (float*)p;
    cudaGetSymbolAddress(&p, g_Asin); float* Asin = (float*)p;
    cudaGetSymbolAddress(&p, g_WT);   float* WT   = (float*)p;

    const long M1 = 1048576L;
    float* sw1T = WT;
    float* sw2T = WT + 2*M1;
    float* mw1T = WT + 4*M1;
    float* mw2T = WT + 8*M1;
    float* cw1T = WT + 12*M1;
    float* cw2T = WT + 16*M1;
    float* fw1T = WT + 20*M1;
    float* fw2T = WT + 28*M1;

    init_fwd<<<(NF*TT + 255)/256, 256>>>();
    init_inv<<<(int)(((long)TT*KI + 255)/256), 256>>>();
    transpose(sw1, sw1T, DD, FFD);
    transpose(sw2, sw2T, FFD, DD);
    transpose(mw1, mw1T, DD, FFD, 2);
    transpose(mw2, mw2T, FFD, DD, 2);
    transpose(cw1, cw1T, DD, FFD, 2);
    transpose(cw2, cw2T, FFD, DD, 2);
    transpose(fw1, fw1T, 2048, FFD, 2);
    transpose(fw2, fw2T, FFD, 2048, 2);
    transpose(x, xT, TT, DD, BSZ);

    router_kernel<<<NTOK, 256>>>(x, rw, rb, gw, gb);
    aux_kernel<<<1, 256>>>(out, out_size);

    const long NEL = (long)NTOK*DD;
    const int EW_BLOCKS = (int)((NEL + 255) / 256);

    // shared expert
    gemm(1, x, sw1T, H,   sb1, NTOK, FFD, DD,  DD,  DD,  FFD);
    gemm(4, H, sw2T, out, sb2, NTOK, DD,  FFD, FFD, FFD, DD);

    // plain MLP experts (eid 2,5)
    for (int j = 0; j < 2; j++) {
        gemm(1, x, mw1T + (long)j*2*M1, H,   mb1 + j*FFD, NTOK, FFD, DD,  DD,  DD,  FFD);
        gemm(3, H, mw2T + (long)j*2*M1, out, mb2 + j*DD,  NTOK, DD,  FFD, FFD, FFD, DD, 1,0,0,0, j==0?2:5);
    }

    // conv experts (eid 0,3)
    for (int j = 0; j < 2; j++) {
        conv_kernel<<<EW_BLOCKS, 256>>>(x, ck + (long)j*DD*3, xc);
        gemm(1, xc, cw1T + (long)j*2*M1, H,   cb1 + j*FFD, NTOK, FFD, DD,  DD,  DD,  FFD);
        gemm(3, H,  cw2T + (long)j*2*M1, out, cb2 + j*DD,  NTOK, DD,  FFD, FFD, FFD, DD, 1,0,0,0, j==0?0:3);
    }

    // fourier experts (eid 1,4)
    gemm(0, Acos, xT, cat,        nullptr, NF, DD, TT, TT, TT, 2048, BSZ, 0, (long)DD*TT, (long)NF*2048);
    gemm(0, Asin, xT, cat + 1024, nullptr, NF, DD, TT, TT, TT, 2048, BSZ, 0, (long)DD*TT, (long)NF*2048);
    for (int j = 0; j < 2; j++) {
        gemm(1, cat, fw1T + (long)j*4*M1, H,  fb1 + j*FFD,  BSZ*NF, FFD,  2048, 2048, 2048, FFD);
        gemm(2, H,   fw2T + (long)j*4*M1, fo, fb2 + j*2048, BSZ*NF, 2048, FFD,  FFD,  FFD,  2048);
        transpose_fo<<<dim3(33, 32, BSZ), dim3(32,8)>>>(fo, foT, 0, 0);
        transpose_fo<<<dim3(33, 32, BSZ), dim3(32,8)>>>(fo, foT, 1024, NFP);
        gemm(5, CiSi, foT, out, nullptr, TT, DD, KI, KI, KI, DD, BSZ, 0, (long)DD*KI, (long)TT*DD, j==0?1:4);
    }
}